// round 5
// baseline (speedup 1.0000x reference)
#include <cuda_runtime.h>
#include <cstdint>

#define BATCH 8
#define NN 2048
#define FF 128

// ---------------- scratch (static device globals; no allocation) ----------------
__device__ float g_h[BATCH * NN * FF];                 // h, then h2 = tf32(h*invD) in place
__device__ float g_s1[BATCH * NN], g_s2p[BATCH * NN];  // s1, s2 + b_a
__device__ float g_u1[BATCH * NN], g_u2[BATCH * NN];   // exp(s1), exp(s2p)
__device__ float g_v1[BATCH * NN], g_v2[BATCH * NN];   // exp(0.2 s1), exp(0.2 s2p)
__device__ float g_DU[BATCH * NN], g_DV[BATCH * NN];   // column partial sums
__device__ unsigned g_mask[BATCH * NN * (NN / 32)];    // adjacency bitmask [b][i][w]

__device__ __forceinline__ unsigned f2tf32(float f) {
    unsigned u;
    asm("cvt.rna.tf32.f32 %0, %1;" : "=r"(u) : "f"(f));
    return u;
}

__device__ __forceinline__ void mma_tf32(float* d, const unsigned* a, const unsigned* b) {
    asm volatile(
        "mma.sync.aligned.m16n8k8.row.col.f32.tf32.tf32.f32 "
        "{%0,%1,%2,%3}, {%4,%5,%6,%7}, {%8,%9}, {%0,%1,%2,%3};\n"
        : "+f"(d[0]), "+f"(d[1]), "+f"(d[2]), "+f"(d[3])
        : "r"(a[0]), "r"(a[1]), "r"(a[2]), "r"(a[3]), "r"(b[0]), "r"(b[1]));
}

#define CP_ASYNC16(dst, src) \
    asm volatile("cp.async.cg.shared.global [%0], [%1], 16;\n" ::"r"(dst), "l"(src))
#define CP_COMMIT() asm volatile("cp.async.commit_group;\n")
#define CP_WAIT(n) asm volatile("cp.async.wait_group %0;\n" ::"n"(n))

// ---------------- kernel 1: h = x @ W + b_W, fused row stats + DU/DV zeroing ----------------
__global__ __launch_bounds__(256) void k_gemm_h(const float* __restrict__ x,
                                                const float* __restrict__ W,
                                                const float* __restrict__ bW,
                                                const float* __restrict__ a1,
                                                const float* __restrict__ a2,
                                                const float* __restrict__ ba) {
    __shared__ float XsT[32][68];   // [k][m] transposed, padded
    __shared__ float Ws[32][128];   // [k][n]
    const int t = threadIdx.x;
    const int tx = t & 15, ty = t >> 4;
    const int m0 = blockIdx.x * 64;

    if (t < 64) {  // zero this block's slice of the column-sum accumulators
        g_DU[m0 + t] = 0.f;
        g_DV[m0 + t] = 0.f;
    }

    float acc[4][8];
#pragma unroll
    for (int i = 0; i < 4; i++)
#pragma unroll
        for (int j = 0; j < 8; j++) acc[i][j] = 0.f;

    for (int k0 = 0; k0 < 128; k0 += 32) {
#pragma unroll
        for (int it = 0; it < 2; it++) {
            int q = t + it * 256;
            int rr = q >> 3, c4 = q & 7;
            float4 v = *(const float4*)&x[(m0 + rr) * 128 + k0 + c4 * 4];
            XsT[c4 * 4 + 0][rr] = v.x;
            XsT[c4 * 4 + 1][rr] = v.y;
            XsT[c4 * 4 + 2][rr] = v.z;
            XsT[c4 * 4 + 3][rr] = v.w;
        }
#pragma unroll
        for (int it = 0; it < 4; it++) {
            int q = t + it * 256;
            int rr = q >> 5, c4 = q & 31;
            *(float4*)&Ws[rr][c4 * 4] = *(const float4*)&W[(k0 + rr) * 128 + c4 * 4];
        }
        __syncthreads();
#pragma unroll
        for (int kk = 0; kk < 32; kk++) {
            float4 a = *(float4*)&XsT[kk][ty * 4];
            float4 b0 = *(float4*)&Ws[kk][tx * 4];
            float4 b1 = *(float4*)&Ws[kk][64 + tx * 4];
            float aa[4] = {a.x, a.y, a.z, a.w};
            float bb[8] = {b0.x, b0.y, b0.z, b0.w, b1.x, b1.y, b1.z, b1.w};
#pragma unroll
            for (int i = 0; i < 4; i++)
#pragma unroll
                for (int j = 0; j < 8; j++) acc[i][j] = fmaf(aa[i], bb[j], acc[i][j]);
        }
        __syncthreads();
    }

    float4 bwA = *(const float4*)&bW[tx * 4];
    float4 bwB = *(const float4*)&bW[64 + tx * 4];
    float4 a1A = *(const float4*)&a1[tx * 4];
    float4 a1B = *(const float4*)&a1[64 + tx * 4];
    float4 a2A = *(const float4*)&a2[tx * 4];
    float4 a2B = *(const float4*)&a2[64 + tx * 4];

    float p1[4], p2[4];
#pragma unroll
    for (int i = 0; i < 4; i++) {
        int row = m0 + ty * 4 + i;
        float4 o0 = {acc[i][0] + bwA.x, acc[i][1] + bwA.y, acc[i][2] + bwA.z, acc[i][3] + bwA.w};
        float4 o1 = {acc[i][4] + bwB.x, acc[i][5] + bwB.y, acc[i][6] + bwB.z, acc[i][7] + bwB.w};
        *(float4*)&g_h[row * 128 + tx * 4] = o0;
        *(float4*)&g_h[row * 128 + 64 + tx * 4] = o1;
        p1[i] = o0.x * a1A.x + o0.y * a1A.y + o0.z * a1A.z + o0.w * a1A.w +
                o1.x * a1B.x + o1.y * a1B.y + o1.z * a1B.z + o1.w * a1B.w;
        p2[i] = o0.x * a2A.x + o0.y * a2A.y + o0.z * a2A.z + o0.w * a2A.w +
                o1.x * a2B.x + o1.y * a2B.y + o1.z * a2B.z + o1.w * a2B.w;
    }
#pragma unroll
    for (int off = 8; off > 0; off >>= 1) {
#pragma unroll
        for (int i = 0; i < 4; i++) {
            p1[i] += __shfl_down_sync(0xffffffffu, p1[i], off);
            p2[i] += __shfl_down_sync(0xffffffffu, p2[i], off);
        }
    }
    if (tx == 0) {
        float ba0 = ba[0];
#pragma unroll
        for (int i = 0; i < 4; i++) {
            int row = m0 + ty * 4 + i;
            float s1v = p1[i];
            float s2pv = p2[i] + ba0;
            g_s1[row] = s1v;
            g_s2p[row] = s2pv;
            g_u1[row] = expf(s1v);
            g_u2[row] = expf(s2pv);
            g_v1[row] = expf(0.2f * s1v);
            g_v2[row] = expf(0.2f * s2pv);
        }
    }
}

// ---------------- kernel 2: fused adj pack (bitmask) + column sums ----------------
// grid (2, 32, 8): x = 1024-col block, y = 64-row chunk, z = batch. 256 thr, 4 cols/thread.
__global__ __launch_bounds__(256) void k_pack(const int* __restrict__ adj) {
    const int t = threadIdx.x;
    const int jb = blockIdx.x, ic = blockIdx.y, b = blockIdx.z;
    const int i0 = ic * 64;
    const int nb = b * NN;
    __shared__ float s1s[64], u1s[64], v1s[64];
    if (t < 64) {
        s1s[t] = g_s1[nb + i0 + t];
        u1s[t] = g_u1[nb + i0 + t];
        v1s[t] = g_v1[nb + i0 + t];
    }
    __syncthreads();

    const int jloc = jb * 1024 + t * 4;
    const int sub = t & 7;
    float s2p[4], accU[4], accV[4];
#pragma unroll
    for (int q = 0; q < 4; q++) {
        s2p[q] = g_s2p[nb + jloc + q];
        accU[q] = 0.f;
        accV[q] = 0.f;
    }
    const int4* arow = (const int4*)(adj + (size_t)b * NN * NN + (size_t)i0 * NN + jb * 1024);
    unsigned* mrow = g_mask + (size_t)(nb + i0) * 64 + jb * 32 + (t >> 3);
    const int stride4 = NN / 4;

#pragma unroll 2
    for (int ii = 0; ii < 64; ii++) {
        int4 av = arow[ii * stride4 + t];
        bool m0 = av.x > 0, m1 = av.y > 0, m2 = av.z > 0, m3 = av.w > 0;
        unsigned nib = (m0 ? 1u : 0u) | (m1 ? 2u : 0u) | (m2 ? 4u : 0u) | (m3 ? 8u : 0u);
        unsigned w = nib << (sub * 4);
        w |= __shfl_xor_sync(0xffffffffu, w, 1);
        w |= __shfl_xor_sync(0xffffffffu, w, 2);
        w |= __shfl_xor_sync(0xffffffffu, w, 4);
        if (sub == 0) mrow[(size_t)ii * 64] = w;

        float s1i = s1s[ii], u1i = u1s[ii], v1i = v1s[ii];
        bool mm[4] = {m0, m1, m2, m3};
#pragma unroll
        for (int q = 0; q < 4; q++) {
            float tt = s1i + s2p[q];
            accU[q] += (mm[q] && tt > 0.f) ? u1i : 0.f;
            accV[q] += (mm[q] && tt <= 0.f) ? v1i : 0.f;
        }
    }
#pragma unroll
    for (int q = 0; q < 4; q++) {
        atomicAdd(&g_DU[nb + jloc + q], accU[q]);
        atomicAdd(&g_DV[nb + jloc + q], accV[q]);
    }
}

// ---------------- kernel 3: h2 = tf32(h * invD[row]) in place (invD fused) ----------------
__global__ __launch_bounds__(256) void k_scale() {
    int idx = blockIdx.x * 256 + threadIdx.x;  // float4 index, 524288 total
    int row = idx >> 5;
    float d = g_u2[row] * g_DU[row] + g_v2[row] * g_DV[row];
    float inv = (d != 0.f) ? (1.f / d) : 0.f;  // guard fully-masked columns
    float4* hp = (float4*)g_h;
    float4 v = hp[idx];
    v.x = __uint_as_float(f2tf32(v.x * inv));
    v.y = __uint_as_float(f2tf32(v.y * inv));
    v.z = __uint_as_float(f2tf32(v.z * inv));
    v.w = __uint_as_float(f2tf32(v.w * inv));
    hp[idx] = v;
}

// ---------------- kernel 4: out = relu(P @ h2), P built from bitmask ----------------
// grid (32, 8): x = 64-row i-block, y = batch. 256 thr = 8 warps: 4(M=16) x 2(N=64).
// Double-buffered cp.async pipeline on the h2 tile.
__global__ __launch_bounds__(256) void k_attn(float* __restrict__ out) {
    extern __shared__ float4 smb[];
    float4* js = smb;                       // [2048]: (s2p, u2, v2, -)
    float* hs = (float*)(smb + NN);         // 2 x [32][136]

    const int b = blockIdx.y;
    const int i0 = blockIdx.x * 64;
    const int t = threadIdx.x;
    const int lane = t & 31, wid = t >> 5;
    const int wm = wid & 3, wn = wid >> 2;
    const int r = lane >> 2, c = lane & 3;
    const int nb = b * NN;

    for (int q = t; q < NN; q += 256)
        js[q] = make_float4(g_s2p[nb + q], g_u2[nb + q], g_v2[nb + q], 0.f);

    const int rA = i0 + wm * 16 + r, rB = rA + 8;
    const float s1A = g_s1[nb + rA], u1A = g_u1[nb + rA], v1A = g_v1[nb + rA];
    const float s1B = g_s1[nb + rB], u1B = g_u1[nb + rB], v1B = g_v1[nb + rB];
    const unsigned* mpA = g_mask + (size_t)(nb + rA) * 64;
    const unsigned* mpB = g_mask + (size_t)(nb + rB) * 64;

    // cp.async mapping: thread loads 4 x 16B of one row
    const int crow = t >> 3, cch = (t & 7) * 4;
    const float* hsrc = g_h + (size_t)nb * FF;

    float acc[8][4];
#pragma unroll
    for (int nt = 0; nt < 8; nt++)
#pragma unroll
        for (int q = 0; q < 4; q++) acc[nt][q] = 0.f;

    // prefetch tile 0
    {
        unsigned dst = (unsigned)__cvta_generic_to_shared(hs + crow * 136 + cch * 4);
        const float* src = hsrc + (size_t)crow * FF + cch * 4;
#pragma unroll
        for (int it = 0; it < 4; it++) CP_ASYNC16(dst + it * 16, src + it * 4);
        CP_COMMIT();
    }

    for (int kt = 0; kt < 64; kt++) {
        if (kt < 63) {
            unsigned dst = (unsigned)__cvta_generic_to_shared(
                hs + ((kt + 1) & 1) * 4352 + crow * 136 + cch * 4);
            const float* src = hsrc + (size_t)((kt + 1) * 32 + crow) * FF + cch * 4;
#pragma unroll
            for (int it = 0; it < 4; it++) CP_ASYNC16(dst + it * 16, src + it * 4);
            CP_COMMIT();
            CP_WAIT(1);
        } else {
            CP_WAIT(0);
        }
        __syncthreads();

        const float* H = hs + (kt & 1) * 4352;
        const unsigned mwA = mpA[kt];
        const unsigned mwB = mpB[kt];
        const float4* jsk = js + kt * 32;

#pragma unroll
        for (int ks = 0; ks < 4; ks++) {
            const int bp = ks * 8 + c;
            float4 ja = jsk[bp];
            float4 jb2 = jsk[bp + 4];

            unsigned afr[4];
            {
                float tt = s1A + ja.x;
                float p = (tt > 0.f) ? u1A * ja.y : v1A * ja.z;
                p = ((mwA >> bp) & 1u) ? p : 0.f;
                afr[0] = f2tf32(p);
            }
            {
                float tt = s1B + ja.x;
                float p = (tt > 0.f) ? u1B * ja.y : v1B * ja.z;
                p = ((mwB >> bp) & 1u) ? p : 0.f;
                afr[1] = f2tf32(p);
            }
            {
                float tt = s1A + jb2.x;
                float p = (tt > 0.f) ? u1A * jb2.y : v1A * jb2.z;
                p = ((mwA >> (bp + 4)) & 1u) ? p : 0.f;
                afr[2] = f2tf32(p);
            }
            {
                float tt = s1B + jb2.x;
                float p = (tt > 0.f) ? u1B * jb2.y : v1B * jb2.z;
                p = ((mwB >> (bp + 4)) & 1u) ? p : 0.f;
                afr[3] = f2tf32(p);
            }

#pragma unroll
            for (int nt = 0; nt < 8; nt++) {
                const int col = wn * 64 + nt * 8 + r;
                unsigned bb[2];
                bb[0] = __float_as_uint(H[bp * 136 + col]);
                bb[1] = __float_as_uint(H[(bp + 4) * 136 + col]);
                mma_tf32(acc[nt], afr, bb);
            }
        }
        __syncthreads();
    }

#pragma unroll
    for (int nt = 0; nt < 8; nt++) {
        int col = wn * 64 + nt * 8 + 2 * c;
        float2 o0 = {fmaxf(acc[nt][0], 0.f), fmaxf(acc[nt][1], 0.f)};
        float2 o1 = {fmaxf(acc[nt][2], 0.f), fmaxf(acc[nt][3], 0.f)};
        *(float2*)&out[(size_t)(nb + rA) * FF + col] = o0;
        *(float2*)&out[(size_t)(nb + rB) * FF + col] = o1;
    }
}

// ---------------- launch ----------------
extern "C" void kernel_launch(void* const* d_in, const int* in_sizes, int n_in,
                              void* d_out, int out_size) {
    const float* x = (const float*)d_in[0];
    const int* adj = (const int*)d_in[1];
    const float* W = (const float*)d_in[2];
    const float* bW = (const float*)d_in[3];
    const float* a1 = (const float*)d_in[4];
    const float* a2 = (const float*)d_in[5];
    const float* ba = (const float*)d_in[6];
    float* out = (float*)d_out;

    const int smem_attn = NN * 16 + 2 * 32 * 136 * 4;  // 32768 + 34816 = 67584 B
    static bool attr_set = false;
    if (!attr_set) {
        cudaFuncSetAttribute(k_attn, cudaFuncAttributeMaxDynamicSharedMemorySize, smem_attn);
        attr_set = true;
    }

    k_gemm_h<<<256, 256>>>(x, W, bW, a1, a2, ba);
    k_pack<<<dim3(2, 32, 8), 256>>>(adj);
    k_scale<<<2048, 256>>>();
    k_attn<<<dim3(32, 8), 256, smem_attn>>>(out);
}

// round 8
// speedup vs baseline: 1.0509x; 1.0509x over previous
#include <cuda_runtime.h>
#include <cstdint>

#define BATCH 8
#define NN 2048
#define FF 128

// ---------------- scratch (static device globals; no allocation) ----------------
__device__ float g_h[BATCH * NN * FF];                 // h, then h2 = tf32(h*invD) in place
__device__ float g_s1[BATCH * NN], g_s2p[BATCH * NN];  // s1, s2 + b_a
__device__ float g_u1[BATCH * NN], g_u2[BATCH * NN];   // exp(s1), exp(s2p)
__device__ float g_v1[BATCH * NN], g_v2[BATCH * NN];   // exp(0.2 s1), exp(0.2 s2p)
__device__ float g_DU[BATCH * NN], g_DV[BATCH * NN];   // column partial sums
__device__ float4 g_js[BATCH * NN];                    // packed j-stats (s2p, u2, v2, 0)
__device__ unsigned g_mask[BATCH * NN * (NN / 32)];    // adjacency bitmask [b][i][w]

__device__ __forceinline__ unsigned f2tf32(float f) {
    unsigned u;
    asm("cvt.rna.tf32.f32 %0, %1;" : "=r"(u) : "f"(f));
    return u;
}

__device__ __forceinline__ void mma_tf32(float* d, const unsigned* a, const unsigned* b) {
    asm volatile(
        "mma.sync.aligned.m16n8k8.row.col.f32.tf32.tf32.f32 "
        "{%0,%1,%2,%3}, {%4,%5,%6,%7}, {%8,%9}, {%0,%1,%2,%3};\n"
        : "+f"(d[0]), "+f"(d[1]), "+f"(d[2]), "+f"(d[3])
        : "r"(a[0]), "r"(a[1]), "r"(a[2]), "r"(a[3]), "r"(b[0]), "r"(b[1]));
}

#define CP_ASYNC16(dst, src) \
    asm volatile("cp.async.cg.shared.global [%0], [%1], 16;\n" ::"r"(dst), "l"(src))
#define CP_COMMIT() asm volatile("cp.async.commit_group;\n")
#define CP_WAIT(n) asm volatile("cp.async.wait_group %0;\n" ::"n"(n))

// ---------------- kernel 1: h = x @ W + b_W, fused row stats + DU/DV zeroing ----------------
__global__ __launch_bounds__(256) void k_gemm_h(const float* __restrict__ x,
                                                const float* __restrict__ W,
                                                const float* __restrict__ bW,
                                                const float* __restrict__ a1,
                                                const float* __restrict__ a2,
                                                const float* __restrict__ ba) {
    __shared__ float XsT[32][68];   // [k][m] transposed, padded
    __shared__ float Ws[32][128];   // [k][n]
    const int t = threadIdx.x;
    const int tx = t & 15, ty = t >> 4;
    const int m0 = blockIdx.x * 64;

    if (t < 64) {  // zero this block's slice of the column-sum accumulators
        g_DU[m0 + t] = 0.f;
        g_DV[m0 + t] = 0.f;
    }

    float acc[4][8];
#pragma unroll
    for (int i = 0; i < 4; i++)
#pragma unroll
        for (int j = 0; j < 8; j++) acc[i][j] = 0.f;

    for (int k0 = 0; k0 < 128; k0 += 32) {
#pragma unroll
        for (int it = 0; it < 2; it++) {
            int q = t + it * 256;
            int rr = q >> 3, c4 = q & 7;
            float4 v = *(const float4*)&x[(m0 + rr) * 128 + k0 + c4 * 4];
            XsT[c4 * 4 + 0][rr] = v.x;
            XsT[c4 * 4 + 1][rr] = v.y;
            XsT[c4 * 4 + 2][rr] = v.z;
            XsT[c4 * 4 + 3][rr] = v.w;
        }
#pragma unroll
        for (int it = 0; it < 4; it++) {
            int q = t + it * 256;
            int rr = q >> 5, c4 = q & 31;
            *(float4*)&Ws[rr][c4 * 4] = *(const float4*)&W[(k0 + rr) * 128 + c4 * 4];
        }
        __syncthreads();
#pragma unroll
        for (int kk = 0; kk < 32; kk++) {
            float4 a = *(float4*)&XsT[kk][ty * 4];
            float4 b0 = *(float4*)&Ws[kk][tx * 4];
            float4 b1 = *(float4*)&Ws[kk][64 + tx * 4];
            float aa[4] = {a.x, a.y, a.z, a.w};
            float bb[8] = {b0.x, b0.y, b0.z, b0.w, b1.x, b1.y, b1.z, b1.w};
#pragma unroll
            for (int i = 0; i < 4; i++)
#pragma unroll
                for (int j = 0; j < 8; j++) acc[i][j] = fmaf(aa[i], bb[j], acc[i][j]);
        }
        __syncthreads();
    }

    float4 bwA = *(const float4*)&bW[tx * 4];
    float4 bwB = *(const float4*)&bW[64 + tx * 4];
    float4 a1A = *(const float4*)&a1[tx * 4];
    float4 a1B = *(const float4*)&a1[64 + tx * 4];
    float4 a2A = *(const float4*)&a2[tx * 4];
    float4 a2B = *(const float4*)&a2[64 + tx * 4];

    float p1[4], p2[4];
#pragma unroll
    for (int i = 0; i < 4; i++) {
        int row = m0 + ty * 4 + i;
        float4 o0 = {acc[i][0] + bwA.x, acc[i][1] + bwA.y, acc[i][2] + bwA.z, acc[i][3] + bwA.w};
        float4 o1 = {acc[i][4] + bwB.x, acc[i][5] + bwB.y, acc[i][6] + bwB.z, acc[i][7] + bwB.w};
        *(float4*)&g_h[row * 128 + tx * 4] = o0;
        *(float4*)&g_h[row * 128 + 64 + tx * 4] = o1;
        p1[i] = o0.x * a1A.x + o0.y * a1A.y + o0.z * a1A.z + o0.w * a1A.w +
                o1.x * a1B.x + o1.y * a1B.y + o1.z * a1B.z + o1.w * a1B.w;
        p2[i] = o0.x * a2A.x + o0.y * a2A.y + o0.z * a2A.z + o0.w * a2A.w +
                o1.x * a2B.x + o1.y * a2B.y + o1.z * a2B.z + o1.w * a2B.w;
    }
#pragma unroll
    for (int off = 8; off > 0; off >>= 1) {
#pragma unroll
        for (int i = 0; i < 4; i++) {
            p1[i] += __shfl_down_sync(0xffffffffu, p1[i], off);
            p2[i] += __shfl_down_sync(0xffffffffu, p2[i], off);
        }
    }
    if (tx == 0) {
        float ba0 = ba[0];
#pragma unroll
        for (int i = 0; i < 4; i++) {
            int row = m0 + ty * 4 + i;
            float s1v = p1[i];
            float s2pv = p2[i] + ba0;
            g_s1[row] = s1v;
            g_s2p[row] = s2pv;
            g_u1[row] = expf(s1v);
            g_u2[row] = expf(s2pv);
            g_v1[row] = expf(0.2f * s1v);
            g_v2[row] = expf(0.2f * s2pv);
        }
    }
}

// ---------------- kernel 2: fused adj pack (bitmask) + column sums ----------------
// grid (2, 32, 8): x = 1024-col block, y = 64-row chunk, z = batch. 256 thr, 4 cols/thread.
__global__ __launch_bounds__(256) void k_pack(const int* __restrict__ adj) {
    const int t = threadIdx.x;
    const int jb = blockIdx.x, ic = blockIdx.y, b = blockIdx.z;
    const int i0 = ic * 64;
    const int nb = b * NN;
    __shared__ float s1s[64], u1s[64], v1s[64];
    if (t < 64) {
        s1s[t] = g_s1[nb + i0 + t];
        u1s[t] = g_u1[nb + i0 + t];
        v1s[t] = g_v1[nb + i0 + t];
    }
    __syncthreads();

    const int jloc = jb * 1024 + t * 4;
    const int sub = t & 7;
    float s2p[4], accU[4], accV[4];
#pragma unroll
    for (int q = 0; q < 4; q++) {
        s2p[q] = g_s2p[nb + jloc + q];
        accU[q] = 0.f;
        accV[q] = 0.f;
    }
    const int4* arow = (const int4*)(adj + (size_t)b * NN * NN + (size_t)i0 * NN + jb * 1024);
    unsigned* mrow = g_mask + (size_t)(nb + i0) * 64 + jb * 32 + (t >> 3);
    const int stride4 = NN / 4;

#pragma unroll 4
    for (int ii = 0; ii < 64; ii++) {
        int4 av = arow[ii * stride4 + t];
        bool m0 = av.x > 0, m1 = av.y > 0, m2 = av.z > 0, m3 = av.w > 0;
        unsigned nib = (m0 ? 1u : 0u) | (m1 ? 2u : 0u) | (m2 ? 4u : 0u) | (m3 ? 8u : 0u);
        unsigned w = nib << (sub * 4);
        w |= __shfl_xor_sync(0xffffffffu, w, 1);
        w |= __shfl_xor_sync(0xffffffffu, w, 2);
        w |= __shfl_xor_sync(0xffffffffu, w, 4);
        if (sub == 0) mrow[(size_t)ii * 64] = w;

        float s1i = s1s[ii], u1i = u1s[ii], v1i = v1s[ii];
        bool mm[4] = {m0, m1, m2, m3};
#pragma unroll
        for (int q = 0; q < 4; q++) {
            float tt = s1i + s2p[q];
            accU[q] += (mm[q] && tt > 0.f) ? u1i : 0.f;
            accV[q] += (mm[q] && tt <= 0.f) ? v1i : 0.f;
        }
    }
#pragma unroll
    for (int q = 0; q < 4; q++) {
        atomicAdd(&g_DU[nb + jloc + q], accU[q]);
        atomicAdd(&g_DV[nb + jloc + q], accV[q]);
    }
}

// ---------------- kernel 3: h2 = tf32(h * invD[row]) in place; pack g_js ----------------
__global__ __launch_bounds__(256) void k_scale() {
    int idx = blockIdx.x * 256 + threadIdx.x;  // float4 index, 524288 total
    int row = idx >> 5;
    float d = g_u2[row] * g_DU[row] + g_v2[row] * g_DV[row];
    float inv = (d != 0.f) ? (1.f / d) : 0.f;  // guard fully-masked columns
    float4* hp = (float4*)g_h;
    float4 v = hp[idx];
    v.x = __uint_as_float(f2tf32(v.x * inv));
    v.y = __uint_as_float(f2tf32(v.y * inv));
    v.z = __uint_as_float(f2tf32(v.z * inv));
    v.w = __uint_as_float(f2tf32(v.w * inv));
    hp[idx] = v;
    if ((idx & 31) == 0) {
        g_js[row] = make_float4(g_s2p[row], g_u2[row], g_v2[row], 0.f);
    }
}

// ---------------- kernel 4: out = relu(P @ h2), P built from bitmask ----------------
// grid (32, 8): x = 64-row i-block, y = batch. 512 thr = 16 warps: 4(M=16) x 4(N=32).
// Double-buffered cp.async on both the h2 tile and the 32-entry j-stats stage.
__global__ __launch_bounds__(512, 2) void k_attn(float* __restrict__ out) {
    extern __shared__ float smraw[];
    float* hs = smraw;                         // 2 x [32][136] floats = 34816 B
    float4* jstage = (float4*)(smraw + 2 * 32 * 136);  // 2 x [32] float4 = 1024 B

    const int b = blockIdx.y;
    const int i0 = blockIdx.x * 64;
    const int t = threadIdx.x;
    const int lane = t & 31, wid = t >> 5;
    const int wm = wid & 3, wn = wid >> 2;
    const int r = lane >> 2, c = lane & 3;
    const int nb = b * NN;

    const int rA = i0 + wm * 16 + r, rB = rA + 8;
    const float s1A = g_s1[nb + rA], u1A = g_u1[nb + rA], v1A = g_v1[nb + rA];
    const float s1B = g_s1[nb + rB], u1B = g_u1[nb + rB], v1B = g_v1[nb + rB];
    const unsigned* mpA = g_mask + (size_t)(nb + rA) * 64;
    const unsigned* mpB = g_mask + (size_t)(nb + rB) * 64;

    const float* hsrc = g_h + (size_t)nb * FF;
    const float4* jsrc = g_js + nb;

    // cp.async mapping: 1024 16B chunks of Hs; each thread does 2. Js: threads 0-31.
    const int q0 = t, q1 = t + 512;
    const int r0 = q0 >> 5, c0 = (q0 & 31) * 4;
    const int r1 = q1 >> 5, c1 = (q1 & 31) * 4;

    float acc[4][4];
#pragma unroll
    for (int nt = 0; nt < 4; nt++)
#pragma unroll
        for (int q = 0; q < 4; q++) acc[nt][q] = 0.f;

    // prefetch tile 0
    {
        unsigned d0 = (unsigned)__cvta_generic_to_shared(hs + r0 * 136 + c0);
        unsigned d1 = (unsigned)__cvta_generic_to_shared(hs + r1 * 136 + c1);
        CP_ASYNC16(d0, hsrc + (size_t)r0 * FF + c0);
        CP_ASYNC16(d1, hsrc + (size_t)r1 * FF + c1);
        if (t < 32) {
            unsigned dj = (unsigned)__cvta_generic_to_shared(jstage + t);
            CP_ASYNC16(dj, jsrc + t);
        }
        CP_COMMIT();
    }

    unsigned mwA = mpA[0], mwB = mpB[0];

    for (int kt = 0; kt < 64; kt++) {
        const int par = kt & 1;
        unsigned mwA_n = 0, mwB_n = 0;
        if (kt < 63) {
            mwA_n = mpA[kt + 1];
            mwB_n = mpB[kt + 1];
            const int nxt = (kt + 1) & 1;
            const size_t koff = (size_t)(kt + 1) * 32;
            unsigned d0 = (unsigned)__cvta_generic_to_shared(hs + nxt * 4352 + r0 * 136 + c0);
            unsigned d1 = (unsigned)__cvta_generic_to_shared(hs + nxt * 4352 + r1 * 136 + c1);
            CP_ASYNC16(d0, hsrc + (koff + r0) * FF + c0);
            CP_ASYNC16(d1, hsrc + (koff + r1) * FF + c1);
            if (t < 32) {
                unsigned dj = (unsigned)__cvta_generic_to_shared(jstage + nxt * 32 + t);
                CP_ASYNC16(dj, jsrc + koff + t);
            }
            CP_COMMIT();
            CP_WAIT(1);
        } else {
            CP_WAIT(0);
        }
        __syncthreads();

        const float* H = hs + par * 4352;
        const float4* J = jstage + par * 32;

#pragma unroll
        for (int ks = 0; ks < 4; ks++) {
            const int bp = ks * 8 + c;
            float4 ja = J[bp];
            float4 jb2 = J[bp + 4];

            unsigned afr[4];
            {
                float tt = s1A + ja.x;
                float p = (tt > 0.f) ? u1A * ja.y : v1A * ja.z;
                p = ((mwA >> bp) & 1u) ? p : 0.f;
                afr[0] = f2tf32(p);
            }
            {
                float tt = s1B + ja.x;
                float p = (tt > 0.f) ? u1B * ja.y : v1B * ja.z;
                p = ((mwB >> bp) & 1u) ? p : 0.f;
                afr[1] = f2tf32(p);
            }
            {
                float tt = s1A + jb2.x;
                float p = (tt > 0.f) ? u1A * jb2.y : v1A * jb2.z;
                p = ((mwA >> (bp + 4)) & 1u) ? p : 0.f;
                afr[2] = f2tf32(p);
            }
            {
                float tt = s1B + jb2.x;
                float p = (tt > 0.f) ? u1B * jb2.y : v1B * jb2.z;
                p = ((mwB >> (bp + 4)) & 1u) ? p : 0.f;
                afr[3] = f2tf32(p);
            }

#pragma unroll
            for (int nt = 0; nt < 4; nt++) {
                const int col = wn * 32 + nt * 8 + r;
                unsigned bb[2];
                bb[0] = __float_as_uint(H[bp * 136 + col]);
                bb[1] = __float_as_uint(H[(bp + 4) * 136 + col]);
                mma_tf32(acc[nt], afr, bb);
            }
        }
        __syncthreads();
        mwA = mwA_n;
        mwB = mwB_n;
    }

#pragma unroll
    for (int nt = 0; nt < 4; nt++) {
        int col = wn * 32 + nt * 8 + 2 * c;
        float2 o0 = {fmaxf(acc[nt][0], 0.f), fmaxf(acc[nt][1], 0.f)};
        float2 o1 = {fmaxf(acc[nt][2], 0.f), fmaxf(acc[nt][3], 0.f)};
        *(float2*)&out[(size_t)(nb + rA) * FF + col] = o0;
        *(float2*)&out[(size_t)(nb + rB) * FF + col] = o1;
    }
}

// ---------------- launch ----------------
extern "C" void kernel_launch(void* const* d_in, const int* in_sizes, int n_in,
                              void* d_out, int out_size) {
    const float* x = (const float*)d_in[0];
    const int* adj = (const int*)d_in[1];
    const float* W = (const float*)d_in[2];
    const float* bW = (const float*)d_in[3];
    const float* a1 = (const float*)d_in[4];
    const float* a2 = (const float*)d_in[5];
    const float* ba = (const float*)d_in[6];
    float* out = (float*)d_out;

    const int smem_attn = 2 * 32 * 136 * 4 + 2 * 32 * 16;  // 34816 + 1024 = 35840 B
    static bool attr_set = false;
    if (!attr_set) {
        cudaFuncSetAttribute(k_attn, cudaFuncAttributeMaxDynamicSharedMemorySize, smem_attn);
        attr_set = true;
    }

    k_gemm_h<<<256, 256>>>(x, W, bW, a1, a2, ba);
    k_pack<<<dim3(2, 32, 8), 256>>>(adj);
    k_scale<<<2048, 256>>>();
    k_attn<<<dim3(32, 8), 512, smem_attn>>>(out);
}